// round 2
// baseline (speedup 1.0000x reference)
#include <cuda_runtime.h>
#include <cuda_bf16.h>

// NonMaximaSuppression2d: x (8, 64, 256, 256) fp32.
// out[p] = x[p] if x[p] > max(0, 8 replicate-padded neighbors) else 0.
//
// One warp spans a full 256-wide row (8 cols/lane as 2x float4).
// Horizontal neighbors via 2 warp shuffles per row (no scalar edge loads).
// Each warp rolls down a 16-row strip keeping 3 rows in registers,
// so each input row is loaded from memory exactly once per strip.

#define H 256
#define W 256
#define ROWS 16
#define STRIPS (H / ROWS)        // 16 strips per image
#define WARPS_PER_BLOCK 8
#define NIMG (8 * 64)            // 512

__device__ __forceinline__ void load_row(const float* __restrict__ base, int y,
                                         int lane, float v[8])
{
    const float4* p = (const float4*)(base + (size_t)y * W) + lane * 2;
    float4 a = __ldg(p);
    float4 b = __ldg(p + 1);
    v[0] = a.x; v[1] = a.y; v[2] = a.z; v[3] = a.w;
    v[4] = b.x; v[5] = b.y; v[6] = b.z; v[7] = b.w;
}

// h2[j] = max(v[j-1], v[j+1]) with replicate padding at image edges,
// cross-lane values fetched by shuffle.
__device__ __forceinline__ void calc_h2(const float v[8], int lane, float h2[8])
{
    float lf = __shfl_up_sync(0xffffffffu, v[7], 1);
    if (lane == 0) lf = v[0];                 // replicate col 0
    float rt = __shfl_down_sync(0xffffffffu, v[0], 1);
    if (lane == 31) rt = v[7];                // replicate col 255

    h2[0] = fmaxf(lf,   v[1]);
#pragma unroll
    for (int j = 1; j < 7; j++)
        h2[j] = fmaxf(v[j-1], v[j+1]);
    h2[7] = fmaxf(v[6], rt);
}

__global__ __launch_bounds__(32 * WARPS_PER_BLOCK)
void nms2d_kernel(const float* __restrict__ x, float* __restrict__ out)
{
    const int warp = threadIdx.x >> 5;
    const int lane = threadIdx.x & 31;
    const int s    = blockIdx.x * WARPS_PER_BLOCK + warp;  // global strip id
    const int b    = s / STRIPS;                           // image
    const int ys   = (s % STRIPS) * ROWS;                  // first output row

    const float* __restrict__ base = x   + (size_t)b * (H * W);
    float*       __restrict__ ob   = out + (size_t)b * (H * W);

    float vp[8], h2p[8];   // prev row (top)
    float vc[8], h2c[8];   // cur row (mid)
    float vn[8], h2n[8];   // next row (bottom)

    const int ym1 = (ys > 0) ? ys - 1 : 0;
    load_row(base, ym1, lane, vp); calc_h2(vp, lane, h2p);
    load_row(base, ys,  lane, vc); calc_h2(vc, lane, h2c);

#pragma unroll 4
    for (int i = 0; i < ROWS; i++) {
        const int y  = ys + i;
        const int yn = (y < H - 1) ? y + 1 : H - 1;
        load_row(base, yn, lane, vn); calc_h2(vn, lane, h2n);

        float o[8];
#pragma unroll
        for (int j = 0; j < 8; j++) {
            const float h3t = fmaxf(h2p[j], vp[j]);   // top 3-max
            const float h3b = fmaxf(h2n[j], vn[j]);   // bottom 3-max
            float mx = fmaxf(h2c[j], 0.0f);           // mid (excl. center), 0-seeded
            mx = fmaxf(mx, fmaxf(h3t, h3b));
            o[j] = (vc[j] > mx) ? vc[j] : 0.0f;
        }

        float4* po = (float4*)(ob + (size_t)y * W) + lane * 2;
        po[0] = make_float4(o[0], o[1], o[2], o[3]);
        po[1] = make_float4(o[4], o[5], o[6], o[7]);

#pragma unroll
        for (int j = 0; j < 8; j++) {
            vp[j] = vc[j]; h2p[j] = h2c[j];
            vc[j] = vn[j]; h2c[j] = h2n[j];
        }
    }
}

extern "C" void kernel_launch(void* const* d_in, const int* in_sizes, int n_in,
                              void* d_out, int out_size)
{
    const float* x = (const float*)d_in[0];
    float* out = (float*)d_out;

    const int total_strips = NIMG * STRIPS;               // 8192 warps
    const int blocks = total_strips / WARPS_PER_BLOCK;    // 1024 blocks
    nms2d_kernel<<<blocks, 32 * WARPS_PER_BLOCK>>>(x, out);
}

// round 3
// speedup vs baseline: 1.1706x; 1.1706x over previous
#include <cuda_runtime.h>
#include <cuda_bf16.h>

// NonMaximaSuppression2d: x (8, 64, 256, 256) fp32.
// out[p] = x[p] if x[p] > max(0, 8 replicate-padded neighbors) else 0.
//
// One warp = one full 256-wide output row; each lane owns 8 columns
// (2x float4). All 6 row-loads per thread are independent (MLP=6).
// Horizontal neighbors: 2 warp shuffles per row. Vertical reuse: L1
// (8 warps/block = 8 adjacent rows share a 10KB window).

#define H 256
#define W 256
#define WARPS_PER_BLOCK 8
#define NIMG (8 * 64)            // 512 images

__device__ __forceinline__ void load_row(const float* __restrict__ row,
                                         int lane, float v[8])
{
    const float4* p = (const float4*)row + lane * 2;
    float4 a = __ldg(p);
    float4 b = __ldg(p + 1);
    v[0] = a.x; v[1] = a.y; v[2] = a.z; v[3] = a.w;
    v[4] = b.x; v[5] = b.y; v[6] = b.z; v[7] = b.w;
}

// h2[j] = max(v[j-1], v[j+1]) with replicate padding at image edges.
__device__ __forceinline__ void calc_h2(const float v[8], int lane, float h2[8])
{
    float lf = __shfl_up_sync(0xffffffffu, v[7], 1);
    if (lane == 0) lf = v[0];                 // replicate col 0
    float rt = __shfl_down_sync(0xffffffffu, v[0], 1);
    if (lane == 31) rt = v[7];                // replicate col 255

    h2[0] = fmaxf(lf,   v[1]);
#pragma unroll
    for (int j = 1; j < 7; j++)
        h2[j] = fmaxf(v[j-1], v[j+1]);
    h2[7] = fmaxf(v[6], rt);
}

__global__ __launch_bounds__(32 * WARPS_PER_BLOCK)
void nms2d_kernel(const float* __restrict__ x, float* __restrict__ out)
{
    const int warp = threadIdx.x >> 5;
    const int lane = threadIdx.x & 31;
    const int r    = blockIdx.x * WARPS_PER_BLOCK + warp;  // global row id
    const int b    = r >> 8;                               // image
    const int y    = r & 255;                              // row in image

    const float* __restrict__ base = x + (size_t)b * (H * W);

    const int yt = (y > 0)     ? y - 1 : 0;
    const int yb = (y < H - 1) ? y + 1 : H - 1;

    // Issue all 6 loads up front — fully independent, MLP = 6.
    float vt[8], vc[8], vb[8];
    load_row(base + (size_t)yt * W, lane, vt);
    load_row(base + (size_t)y  * W, lane, vc);
    load_row(base + (size_t)yb * W, lane, vb);

    float h2t[8], h2c[8], h2b[8];
    calc_h2(vt, lane, h2t);
    calc_h2(vc, lane, h2c);
    calc_h2(vb, lane, h2b);

    float o[8];
#pragma unroll
    for (int j = 0; j < 8; j++) {
        const float h3t = fmaxf(h2t[j], vt[j]);   // top 3-wide max
        const float h3b = fmaxf(h2b[j], vb[j]);   // bottom 3-wide max
        float mx = fmaxf(h2c[j], 0.0f);           // mid (excl. center), 0-seeded
        mx = fmaxf(mx, fmaxf(h3t, h3b));
        o[j] = (vc[j] > mx) ? vc[j] : 0.0f;
    }

    float4* po = (float4*)(out + (size_t)b * (H * W) + (size_t)y * W) + lane * 2;
    po[0] = make_float4(o[0], o[1], o[2], o[3]);
    po[1] = make_float4(o[4], o[5], o[6], o[7]);
}

extern "C" void kernel_launch(void* const* d_in, const int* in_sizes, int n_in,
                              void* d_out, int out_size)
{
    const float* x = (const float*)d_in[0];
    float* out = (float*)d_out;

    const int total_rows = NIMG * H;                    // 131072 warps
    const int blocks = total_rows / WARPS_PER_BLOCK;    // 16384 blocks
    nms2d_kernel<<<blocks, 32 * WARPS_PER_BLOCK>>>(x, out);
}

// round 4
// speedup vs baseline: 1.2177x; 1.0402x over previous
#include <cuda_runtime.h>
#include <cuda_bf16.h>

// NonMaximaSuppression2d: x (8, 64, 256, 256) fp32.
// out[p] = x[p] if x[p] > max(0, 8 replicate-padded neighbors) else 0.
//
// One warp = TWO adjacent 256-wide output rows; each lane owns 8 columns
// (2x float4). 8 fully-independent LDG.128 per thread (rows y-1..y+2),
// MLP=8. Horizontal neighbors via 2 shuffles per row. Vertical halo
// amortized in registers: 4 rows loaded per 2 rows produced (2x amp
// instead of 3x) -> 25% less l1tex traffic than 1-row-per-warp.

#define H 256
#define W 256
#define WARPS_PER_BLOCK 8
#define NIMG (8 * 64)            // 512 images
#define PAIRS_PER_IMG (H / 2)    // 128 row-pairs

__device__ __forceinline__ void load_row(const float* __restrict__ row,
                                         int lane, float v[8])
{
    const float4* p = (const float4*)row + lane * 2;
    float4 a = __ldg(p);
    float4 b = __ldg(p + 1);
    v[0] = a.x; v[1] = a.y; v[2] = a.z; v[3] = a.w;
    v[4] = b.x; v[5] = b.y; v[6] = b.z; v[7] = b.w;
}

// h2[j] = max(v[j-1], v[j+1]) with replicate padding at image edges.
__device__ __forceinline__ void calc_h2(const float v[8], int lane, float h2[8])
{
    float lf = __shfl_up_sync(0xffffffffu, v[7], 1);
    if (lane == 0) lf = v[0];                 // replicate col 0
    float rt = __shfl_down_sync(0xffffffffu, v[0], 1);
    if (lane == 31) rt = v[7];                // replicate col 255

    h2[0] = fmaxf(lf,   v[1]);
#pragma unroll
    for (int j = 1; j < 7; j++)
        h2[j] = fmaxf(v[j-1], v[j+1]);
    h2[7] = fmaxf(v[6], rt);
}

__global__ __launch_bounds__(32 * WARPS_PER_BLOCK, 4)
void nms2d_kernel(const float* __restrict__ x, float* __restrict__ out)
{
    const int warp = threadIdx.x >> 5;
    const int lane = threadIdx.x & 31;
    const int r    = blockIdx.x * WARPS_PER_BLOCK + warp;  // global row-pair id
    const int b    = r >> 7;                               // image
    const int yp   = (r & 127) * 2;                        // first output row

    const float* __restrict__ base = x + (size_t)b * (H * W);

    const int ya = (yp > 0) ? yp - 1 : 0;          // top halo
    const int yd = (yp + 2 < H) ? yp + 2 : H - 1;  // bottom halo

    // 8 independent LDG.128 — all issued before any dependent math.
    float v0[8], v1[8], v2[8], v3[8];
    load_row(base + (size_t)ya       * W, lane, v0);
    load_row(base + (size_t)yp       * W, lane, v1);
    load_row(base + (size_t)(yp + 1) * W, lane, v2);
    load_row(base + (size_t)yd       * W, lane, v3);

    float h20[8], h21[8], h22[8], h23[8];
    calc_h2(v0, lane, h20);
    calc_h2(v1, lane, h21);
    calc_h2(v2, lane, h22);
    calc_h2(v3, lane, h23);

    float oa[8], ob[8];
#pragma unroll
    for (int j = 0; j < 8; j++) {
        const float h30 = fmaxf(h20[j], v0[j]);   // row0 3-wide max
        const float h31 = fmaxf(h21[j], v1[j]);   // row1 3-wide max
        const float h32 = fmaxf(h22[j], v2[j]);   // row2 3-wide max
        const float h33 = fmaxf(h23[j], v3[j]);   // row3 3-wide max

        // output row yp: top=row0, mid=row1, bottom=row2
        float mxa = fmaxf(fmaxf(h21[j], 0.0f), fmaxf(h30, h32));
        oa[j] = (v1[j] > mxa) ? v1[j] : 0.0f;

        // output row yp+1: top=row1, mid=row2, bottom=row3
        float mxb = fmaxf(fmaxf(h22[j], 0.0f), fmaxf(h31, h33));
        ob[j] = (v2[j] > mxb) ? v2[j] : 0.0f;
    }

    float* obase = out + (size_t)b * (H * W);
    float4* pa = (float4*)(obase + (size_t)yp * W) + lane * 2;
    pa[0] = make_float4(oa[0], oa[1], oa[2], oa[3]);
    pa[1] = make_float4(oa[4], oa[5], oa[6], oa[7]);
    float4* pb = (float4*)(obase + (size_t)(yp + 1) * W) + lane * 2;
    pb[0] = make_float4(ob[0], ob[1], ob[2], ob[3]);
    pb[1] = make_float4(ob[4], ob[5], ob[6], ob[7]);
}

extern "C" void kernel_launch(void* const* d_in, const int* in_sizes, int n_in,
                              void* d_out, int out_size)
{
    const float* x = (const float*)d_in[0];
    float* out = (float*)d_out;

    const int total_pairs = NIMG * PAIRS_PER_IMG;        // 65536 warps
    const int blocks = total_pairs / WARPS_PER_BLOCK;    // 8192 blocks
    nms2d_kernel<<<blocks, 32 * WARPS_PER_BLOCK>>>(x, out);
}